// round 4
// baseline (speedup 1.0000x reference)
#include <cuda_runtime.h>
#include <math.h>
#include <stdint.h>

// Problem dims
#define BB   32
#define TT   14
#define MM   2048
#define QD   768
#define KVD  1024
#define HH   12
#define HD   64
#define FFD  3072
#define BT_ROWS 448   // B*T
#define RH      168   // T*H
#define NATTN (BB*TT*HH*MM)   // 11010048

// -------- scratch (device globals; no allocation allowed) --------
__device__ float g_Q  [BT_ROWS*QD];
__device__ float g_qb [BT_ROWS*HH];
__device__ float g_Qt [BT_ROWS*HH*KVD];
__device__ float g_ctx[BT_ROWS*HH*KVD];
__device__ float g_ao [BT_ROWS*QD];
__device__ float g_x  [BT_ROWS*QD];
__device__ float g_hid[BT_ROWS*FFD];
__device__ float g_y  [BT_ROWS*QD];

__device__ __forceinline__ float f2tf_f(float f) {
    uint32_t r;
    asm("cvt.rna.tf32.f32 %0, %1;" : "=r"(r) : "f"(f));
    return __uint_as_float(r);
}

#define MMA_OP(ACC, A0, A1, A2, A3, B0, B1)                                   \
    asm volatile(                                                              \
        "mma.sync.aligned.m16n8k8.row.col.f32.tf32.tf32.f32 "                  \
        "{%0,%1,%2,%3}, {%4,%5,%6,%7}, {%8,%9}, {%0,%1,%2,%3};"                \
        : "+f"((ACC)[0]), "+f"((ACC)[1]), "+f"((ACC)[2]), "+f"((ACC)[3])       \
        : "r"(A0), "r"(A1), "r"(A2), "r"(A3), "r"(B0), "r"(B1))

// ============================================================================
// TF32 tensor-core GEMM. Register-staged, tf32-converted-in-smem, 2-stage
// pipeline with distance-1 LDG prefetch overlapping MMA.
//   C[m,n] = sum_k A[m,k] * B'[k,n]  (per batch z)
//   TRB=false: B'[k,n] = Bp[k*ldb + n]   ("NN", smem [k][BN+8], raw k)
//   TRB=true : B'[k,n] = Bp[n*ldb + k]   ("NT", smem [n][36], permuted k)
// A smem [m][36], permuted k' = (k&3)*8 + (k>>2)  -> vectorized frag loads.
// EPI: 0=none, 1=+colbias, 2=relu(+colbias), 3=(acc+rowbias)*scale
// Warp tile 32x32. K%32==0, N%BN==0; M guarded.
// ============================================================================
template<int BM, int BN, bool TRB, int EPI>
__global__ void __launch_bounds__((BM/32)*(BN/32)*32, 2)
mma_gemm(const float* __restrict__ A, int lda, long aBS,
         const float* __restrict__ Bp, int ldb, long bBS,
         float* __restrict__ C, int ldc, long cBS,
         const float* __restrict__ bias, int biasBS,
         int Mrows, float scale, int K)
{
    constexpr int NWARP = (BM/32)*(BN/32);
    constexpr int NTH   = NWARP*32;
    constexpr int AST   = BM*36;                    // floats per A stage
    constexpr int BST   = TRB ? BN*36 : 32*(BN+8);  // floats per B stage
    constexpr int ACH   = (BM*8)/NTH;               // A float4 per thread
    constexpr int BCH   = TRB ? (BN*8)/NTH : (32*(BN/4))/NTH;

    extern __shared__ float smem[];
    float* As = smem;               // 2 stages
    float* Bs = smem + 2*AST;

    const int bz = blockIdx.z;
    A  += (long)bz * aBS;
    Bp += (long)bz * bBS;
    C  += (long)bz * cBS;
    if (bias) bias += (long)bz * biasBS;

    const int row0 = blockIdx.y * BM;
    const int col0 = blockIdx.x * BN;
    const int tid  = threadIdx.x;
    const int lane = tid & 31;
    const int warp = tid >> 5;
    const int wm   = warp / (BN/32);
    const int wn   = warp % (BN/32);
    const int g    = lane >> 2;
    const int tg   = lane & 3;

    float4 ar[ACH], br[BCH];

    auto ldg_tile = [&](int k0) {
#pragma unroll
        for (int ch = 0; ch < ACH; ch++) {
            int i = tid + ch*NTH;
            int m = i >> 3, q = i & 7;
            int gm = row0 + m;
            ar[ch] = (gm < Mrows)
                ? *(const float4*)(A + (long)gm*lda + k0 + q*4)
                : make_float4(0.f, 0.f, 0.f, 0.f);
        }
        if (TRB) {
#pragma unroll
            for (int ch = 0; ch < BCH; ch++) {
                int i = tid + ch*NTH;
                int n = i >> 3, q = i & 7;
                br[ch] = *(const float4*)(Bp + (long)(col0+n)*ldb + k0 + q*4);
            }
        } else {
#pragma unroll
            for (int ch = 0; ch < BCH; ch++) {
                int i = tid + ch*NTH;
                int k = i / (BN/4), nq = i % (BN/4);
                br[ch] = *(const float4*)(Bp + (long)(k0+k)*ldb + col0 + nq*4);
            }
        }
    };

    auto sts_tile = [&](int st) {
        float* a_s = As + st*AST;
        float* b_s = Bs + st*BST;
#pragma unroll
        for (int ch = 0; ch < ACH; ch++) {
            int i = tid + ch*NTH;
            int m = i >> 3, q = i & 7;
            a_s[m*36 +      q] = f2tf_f(ar[ch].x);
            a_s[m*36 +  8 + q] = f2tf_f(ar[ch].y);
            a_s[m*36 + 16 + q] = f2tf_f(ar[ch].z);
            a_s[m*36 + 24 + q] = f2tf_f(ar[ch].w);
        }
        if (TRB) {
#pragma unroll
            for (int ch = 0; ch < BCH; ch++) {
                int i = tid + ch*NTH;
                int n = i >> 3, q = i & 7;
                b_s[n*36 +      q] = f2tf_f(br[ch].x);
                b_s[n*36 +  8 + q] = f2tf_f(br[ch].y);
                b_s[n*36 + 16 + q] = f2tf_f(br[ch].z);
                b_s[n*36 + 24 + q] = f2tf_f(br[ch].w);
            }
        } else {
#pragma unroll
            for (int ch = 0; ch < BCH; ch++) {
                int i = tid + ch*NTH;
                int k = i / (BN/4), nq = i % (BN/4);
                float4 v = br[ch];
                float4 c = make_float4(f2tf_f(v.x), f2tf_f(v.y),
                                       f2tf_f(v.z), f2tf_f(v.w));
                *(float4*)&b_s[k*(BN+8) + nq*4] = c;
            }
        }
    };

    float acc[2][4][4];
#pragma unroll
    for (int i = 0; i < 2; i++)
#pragma unroll
        for (int j = 0; j < 4; j++)
#pragma unroll
            for (int r = 0; r < 4; r++) acc[i][j][r] = 0.f;

    const int nk = K/32;
    ldg_tile(0);

    for (int t = 0; t < nk; t++) {
        sts_tile(t & 1);
        __syncthreads();
        if (t + 1 < nk) ldg_tile((t+1)*32);   // lands during MMA below

        const float* a_s = As + (t&1)*AST;
        const float* b_s = Bs + (t&1)*BST;

        // A fragment vectors: avr[i][h][idx], idx = 2*kk + half
        uint32_t avr[2][2][8];
#pragma unroll
        for (int i = 0; i < 2; i++) {
            int r = wm*32 + i*16;
            *(uint4*)&avr[i][0][0] = *(const uint4*)&a_s[(r+g  )*36 + tg*8];
            *(uint4*)&avr[i][0][4] = *(const uint4*)&a_s[(r+g  )*36 + tg*8 + 4];
            *(uint4*)&avr[i][1][0] = *(const uint4*)&a_s[(r+g+8)*36 + tg*8];
            *(uint4*)&avr[i][1][4] = *(const uint4*)&a_s[(r+g+8)*36 + tg*8 + 4];
        }

        if (TRB) {
#pragma unroll
            for (int jp = 0; jp < 2; jp++) {
                uint32_t bvr[2][8];
#pragma unroll
                for (int j2 = 0; j2 < 2; j2++) {
                    int n = wn*32 + (jp*2 + j2)*8 + g;
                    *(uint4*)&bvr[j2][0] = *(const uint4*)&b_s[n*36 + tg*8];
                    *(uint4*)&bvr[j2][4] = *(const uint4*)&b_s[n*36 + tg*8 + 4];
                }
#pragma unroll
                for (int kk = 0; kk < 4; kk++)
#pragma unroll
                    for (int j2 = 0; j2 < 2; j2++)
#pragma unroll
                        for (int i = 0; i < 2; i++)
                            MMA_OP(acc[i][jp*2+j2],
                                   avr[i][0][2*kk], avr[i][1][2*kk],
                                   avr[i][0][2*kk+1], avr[i][1][2*kk+1],
                                   bvr[j2][2*kk], bvr[j2][2*kk+1]);
            }
        } else {
#pragma unroll
            for (int kk = 0; kk < 4; kk++)
#pragma unroll
                for (int j = 0; j < 4; j++) {
                    int n = wn*32 + j*8 + g;
                    uint32_t b0 = __float_as_uint(b_s[(kk*8+tg  )*(BN+8) + n]);
                    uint32_t b1 = __float_as_uint(b_s[(kk*8+tg+4)*(BN+8) + n]);
#pragma unroll
                    for (int i = 0; i < 2; i++)
                        MMA_OP(acc[i][j],
                               avr[i][0][2*kk], avr[i][1][2*kk],
                               avr[i][0][2*kk+1], avr[i][1][2*kk+1],
                               b0, b1);
                }
        }
    }

    // ---- epilogue ----
#pragma unroll
    for (int i = 0; i < 2; i++) {
        int r0 = row0 + wm*32 + i*16 + g;
#pragma unroll
        for (int rr = 0; rr < 2; rr++) {
            int gm = r0 + rr*8;
            if (gm >= Mrows) continue;
            float rb = (EPI == 3) ? bias[gm] : 0.f;
#pragma unroll
            for (int j = 0; j < 4; j++) {
                int cn = col0 + wn*32 + j*8 + 2*tg;
                float v0 = acc[i][j][rr*2 + 0];
                float v1 = acc[i][j][rr*2 + 1];
                if (EPI == 1)      { v0 += bias[cn]; v1 += bias[cn+1]; }
                else if (EPI == 2) { v0 = fmaxf(v0 + bias[cn], 0.f);
                                     v1 = fmaxf(v1 + bias[cn+1], 0.f); }
                else if (EPI == 3) { v0 = (v0 + rb) * scale; v1 = (v1 + rb) * scale; }
                *(float2*)(C + (long)gm*ldc + cn) = make_float2(v0, v1);
            }
        }
    }
}

// qb[bt,h] = sum_d Q[bt, h*64+d] * bK[h*64+d]
__global__ void qb_k(const float* __restrict__ Q, const float* __restrict__ bK,
                     float* __restrict__ qb)
{
    int idx = blockIdx.x*blockDim.x + threadIdx.x;
    if (idx >= BT_ROWS*HH) return;
    int bt = idx / HH, h = idx % HH;
    const float* q  = Q  + (long)bt*QD + h*HD;
    const float* bk = bK + h*HD;
    float s = 0.f;
#pragma unroll 8
    for (int d = 0; d < HD; d++) s = fmaf(q[d], bk[d], s);
    qb[idx] = s;
}

// in-place softmax over rows of length 2048
__global__ void softmax_k(float* __restrict__ attn)
{
    float* p = attn + (long)blockIdx.x * MM;
    int tid = threadIdx.x;
    int lane = tid & 31, w = tid >> 5;
    __shared__ float red[8];

    float v[8];
    float mx = -1e30f;
#pragma unroll
    for (int i = 0; i < 8; i++) { v[i] = p[tid + 256*i]; mx = fmaxf(mx, v[i]); }
#pragma unroll
    for (int o = 16; o; o >>= 1) mx = fmaxf(mx, __shfl_xor_sync(0xffffffffu, mx, o));
    if (lane == 0) red[w] = mx;
    __syncthreads();
    mx = red[0];
#pragma unroll
    for (int i = 1; i < 8; i++) mx = fmaxf(mx, red[i]);
    __syncthreads();

    float s = 0.f;
#pragma unroll
    for (int i = 0; i < 8; i++) { v[i] = __expf(v[i] - mx); s += v[i]; }
#pragma unroll
    for (int o = 16; o; o >>= 1) s += __shfl_xor_sync(0xffffffffu, s, o);
    if (lane == 0) red[w] = s;
    __syncthreads();
    float tot = 0.f;
#pragma unroll
    for (int i = 0; i < 8; i++) tot += red[i];

    float inv = 1.f / tot;
#pragma unroll
    for (int i = 0; i < 8; i++) p[tid + 256*i] = v[i] * inv;
}

// out[row,:] = LN(a[row,:] + b[row,:]) * g + be   (row length 768)
__global__ void ln_k(const float* __restrict__ a, const float* __restrict__ b,
                     const float* __restrict__ g, const float* __restrict__ be,
                     float* __restrict__ out)
{
    long row = blockIdx.x;
    int tid = threadIdx.x;
    int lane = tid & 31, w = tid >> 5;
    const float* pa = a + row*QD;
    const float* pb = b + row*QD;
    __shared__ float red[8];

    float v[3];
    float s = 0.f;
#pragma unroll
    for (int i = 0; i < 3; i++) { v[i] = pa[tid + 256*i] + pb[tid + 256*i]; s += v[i]; }
#pragma unroll
    for (int o = 16; o; o >>= 1) s += __shfl_xor_sync(0xffffffffu, s, o);
    if (lane == 0) red[w] = s;
    __syncthreads();
    float tot = 0.f;
#pragma unroll
    for (int i = 0; i < 8; i++) tot += red[i];
    float mu = tot * (1.f/768.f);
    __syncthreads();

    float sq = 0.f;
#pragma unroll
    for (int i = 0; i < 3; i++) { float d = v[i] - mu; sq = fmaf(d, d, sq); }
#pragma unroll
    for (int o = 16; o; o >>= 1) sq += __shfl_xor_sync(0xffffffffu, sq, o);
    if (lane == 0) red[w] = sq;
    __syncthreads();
    float vtot = 0.f;
#pragma unroll
    for (int i = 0; i < 8; i++) vtot += red[i];
    float inv = rsqrtf(vtot * (1.f/768.f) + 1e-5f);

#pragma unroll
    for (int i = 0; i < 3; i++) {
        int c = tid + 256*i;
        out[row*QD + c] = (v[i] - mu) * inv * g[c] + be[c];
    }
}

// smem byte sizes per instantiation (2 stages)
template<int BM, int BN, bool TRB>
constexpr int smem_bytes() {
    return 2 * (BM*36 + (TRB ? BN*36 : 32*(BN+8))) * 4;
}

extern "C" void kernel_launch(void* const* d_in, const int* in_sizes, int n_in,
                              void* d_out_v, int out_size)
{
    const float* expert = (const float*)d_in[0];
    const float* kv     = (const float*)d_in[1];
    const float* WQ  = (const float*)d_in[2];
    const float* bQ  = (const float*)d_in[3];
    const float* WK  = (const float*)d_in[4];
    const float* bK  = (const float*)d_in[5];
    const float* WV  = (const float*)d_in[6];
    const float* bV  = (const float*)d_in[7];
    const float* W1  = (const float*)d_in[8];
    const float* b1  = (const float*)d_in[9];
    const float* W2  = (const float*)d_in[10];
    const float* b2  = (const float*)d_in[11];
    const float* g1  = (const float*)d_in[12];
    const float* be1 = (const float*)d_in[13];
    const float* g2  = (const float*)d_in[14];
    const float* be2 = (const float*)d_in[15];

    float* out   = (float*)d_out_v;
    float* attnw = out + ((long)out_size - (long)NATTN);

    float *Q, *qb, *Qt, *ctx, *ao, *x, *hid, *y;
    cudaGetSymbolAddress((void**)&Q,   g_Q);
    cudaGetSymbolAddress((void**)&qb,  g_qb);
    cudaGetSymbolAddress((void**)&Qt,  g_Qt);
    cudaGetSymbolAddress((void**)&ctx, g_ctx);
    cudaGetSymbolAddress((void**)&ao,  g_ao);
    cudaGetSymbolAddress((void**)&x,   g_x);
    cudaGetSymbolAddress((void**)&hid, g_hid);
    cudaGetSymbolAddress((void**)&y,   g_y);

    cudaFuncSetAttribute(mma_gemm<32,128,false,1>, cudaFuncAttributeMaxDynamicSharedMemorySize, smem_bytes<32,128,false>());
    cudaFuncSetAttribute(mma_gemm<64,128,true, 0>, cudaFuncAttributeMaxDynamicSharedMemorySize, smem_bytes<64,128,true>());
    cudaFuncSetAttribute(mma_gemm<64,128,true, 3>, cudaFuncAttributeMaxDynamicSharedMemorySize, smem_bytes<64,128,true>());
    cudaFuncSetAttribute(mma_gemm<64,128,false,0>, cudaFuncAttributeMaxDynamicSharedMemorySize, smem_bytes<64,128,false>());
    cudaFuncSetAttribute(mma_gemm<64, 64,false,1>, cudaFuncAttributeMaxDynamicSharedMemorySize, smem_bytes<64,64,false>());
    cudaFuncSetAttribute(mma_gemm<64,128,false,2>, cudaFuncAttributeMaxDynamicSharedMemorySize, smem_bytes<64,128,false>());
    cudaFuncSetAttribute(mma_gemm<64,128,false,1>, cudaFuncAttributeMaxDynamicSharedMemorySize, smem_bytes<64,128,false>());

    // 1) Q projection (batched over t): Q[bt,q] = expert[b,t,:]@WQ[t] + bQ[t]
    mma_gemm<32,128,false,1><<<dim3(QD/128, 1, TT), 128, smem_bytes<32,128,false>()>>>(
        expert, TT*QD, (long)QD,
        WQ, QD, (long)QD*QD,
        Q, TT*QD, (long)QD,
        bQ, QD, BB, 1.f, QD);

    // 2) qb = per-head Q . bK
    qb_k<<<(BT_ROWS*HH)/256, 256>>>(Q, bK, qb);

    // 3) Qt[bt,h,c] = sum_d Q[bt,h*64+d] * WK[c,h*64+d]   (batched over h, NT)
    mma_gemm<64,128,true,0><<<dim3(KVD/128, 7, HH), 256, smem_bytes<64,128,true>()>>>(
        Q, QD, (long)HD,
        WK, QD, (long)HD,
        Qt, HH*KVD, (long)KVD,
        nullptr, 0, BT_ROWS, 1.f, HD);

    // 4) scores[b,(t,h),m] = (Qt . kv + qb) / 8   (batched over b, NT)
    mma_gemm<64,128,true,3><<<dim3(MM/128, 3, BB), 256, smem_bytes<64,128,true>()>>>(
        Qt, KVD, (long)RH*KVD,
        kv, KVD, (long)MM*KVD,
        attnw, MM, (long)RH*MM,
        qb, RH, RH, 0.125f, KVD);

    // 5) softmax over m (in place)
    softmax_k<<<BB*TT*HH, 256>>>(attnw);

    // 6) ctx[b,(t,h),c] = attn_w . kv   (batched over b, NN)
    mma_gemm<64,128,false,0><<<dim3(KVD/128, 3, BB), 256, smem_bytes<64,128,false>()>>>(
        attnw, MM, (long)RH*MM,
        kv, KVD, (long)MM*KVD,
        ctx, KVD, (long)RH*KVD,
        nullptr, 0, RH, 1.f, MM);

    // 7) attn_out[bt, h*64+n] = ctx[bt,h,:] @ WV[:, h*64+n] + bV  (batched over h)
    mma_gemm<64,64,false,1><<<dim3(1, 7, HH), 128, smem_bytes<64,64,false>()>>>(
        ctx, HH*KVD, (long)KVD,
        WV, QD, (long)HD,
        ao, QD, (long)HD,
        bV, HD, BT_ROWS, 1.f, KVD);

    // 8) x = LN1(expert + attn_out)
    ln_k<<<BT_ROWS, 256>>>(expert, ao, g1, be1, x);

    // 9) hidden = relu(x @ W1 + b1)
    mma_gemm<64,128,false,2><<<dim3(FFD/128, 7, 1), 256, smem_bytes<64,128,false>()>>>(
        x, QD, 0,
        W1, FFD, 0,
        hid, FFD, 0,
        b1, 0, BT_ROWS, 1.f, QD);

    // 10) y = hidden @ W2 + b2
    mma_gemm<64,128,false,1><<<dim3(QD/128, 7, 1), 256, smem_bytes<64,128,false>()>>>(
        hid, FFD, 0,
        W2, QD, 0,
        y, QD, 0,
        b2, 0, BT_ROWS, 1.f, FFD);

    // 11) out = LN2(x + y)
    ln_k<<<BT_ROWS, 256>>>(x, y, g2, be2, out);
}

// round 6
// speedup vs baseline: 1.3239x; 1.3239x over previous
#include <cuda_runtime.h>
#include <math.h>
#include <stdint.h>

// Problem dims
#define BB   32
#define TT   14
#define MM   2048
#define QD   768
#define KVD  1024
#define HH   12
#define HD   64
#define FFD  3072
#define BT_ROWS 448   // B*T
#define RH      168   // T*H
#define NATTN (BB*TT*HH*MM)   // 11010048

// -------- scratch (device globals; no allocation allowed) --------
__device__ float g_Q  [BT_ROWS*QD];
__device__ float g_qb [BT_ROWS*HH];
__device__ float g_Qt [BT_ROWS*HH*KVD];
__device__ float g_ctx[BT_ROWS*HH*KVD];
__device__ float g_ao [BT_ROWS*QD];
__device__ float g_x  [BT_ROWS*QD];
__device__ float g_hid[BT_ROWS*FFD];
__device__ float g_y  [BT_ROWS*QD];

__device__ __forceinline__ void cp16(uint32_t dst, const float* src, bool pred) {
    asm volatile("cp.async.cg.shared.global [%0], [%1], 16, %2;"
                 :: "r"(dst), "l"(src), "r"(pred ? 16 : 0));
}
__device__ __forceinline__ void cp_commit() {
    asm volatile("cp.async.commit_group;" ::: "memory");
}
__device__ __forceinline__ void cp_wait1() {
    asm volatile("cp.async.wait_group 1;" ::: "memory");
}

// ============================================================================
// TF32 tensor-core GEMM, 3-stage cp.async pipeline. Fragments feed raw fp32
// bits to mma.sync.tf32 (hardware reads tf32 bit positions — no cvt needed).
//   C[m,n] = sum_k A[m,k] * B'[k,n]  (per batch z)
//   TRB=false: B'[k,n] = Bp[k*ldb + n]   ("NN")
//   TRB=true : B'[k,n] = Bp[n*ldb + k]   ("NT")
// EPI: 0=none, 1=+colbias, 2=relu(+colbias), 3=(acc+rowbias)*scale
// BK=32. Warp tile WM x 32. K%32==0, N%BN==0; M guarded.
// ============================================================================
template<int BM, int BN, int WM, bool TRB, int EPI>
__global__ void __launch_bounds__((BM/WM)*(BN/32)*32)
mma_gemm(const float* __restrict__ A, int lda, long aBS,
         const float* __restrict__ Bp, int ldb, long bBS,
         float* __restrict__ C, int ldc, long cBS,
         const float* __restrict__ bias, int biasBS,
         int Mrows, float scale, int K)
{
    constexpr int NWARP = (BM/WM)*(BN/32);
    constexpr int NTH   = NWARP*32;
    constexpr int AST   = BM*36;                    // floats per A stage
    constexpr int BST   = TRB ? BN*36 : 32*(BN+8);  // floats per B stage
    constexpr int MC    = WM/16;                    // m-chunks per warp

    extern __shared__ float smem[];
    float* As = smem;
    float* Bs = smem + 3*AST;
    uint32_t s_as = (uint32_t)__cvta_generic_to_shared(As);
    uint32_t s_bs = (uint32_t)__cvta_generic_to_shared(Bs);

    const int bz = blockIdx.z;
    A  += (long)bz * aBS;
    Bp += (long)bz * bBS;
    C  += (long)bz * cBS;
    if (bias) bias += (long)bz * biasBS;

    const int row0 = blockIdx.y * BM;
    const int col0 = blockIdx.x * BN;
    const int tid  = threadIdx.x;
    const int lane = tid & 31;
    const int warp = tid >> 5;
    const int wm   = warp / (BN/32);
    const int wn   = warp % (BN/32);
    const int g    = lane >> 2;
    const int tg   = lane & 3;

    auto stage_load = [&](int st, int k0) {
#pragma unroll
        for (int it = 0; it < (BM*8)/NTH; it++) {
            int i = tid + it*NTH;
            int m = i >> 3, q = i & 7;
            cp16(s_as + (uint32_t)(st*AST + m*36 + q*4)*4,
                 A + (long)(row0+m)*lda + k0 + q*4,
                 (row0 + m) < Mrows);
        }
        if (TRB) {
#pragma unroll
            for (int it = 0; it < (BN*8)/NTH; it++) {
                int i = tid + it*NTH;
                int n = i >> 3, q = i & 7;
                cp16(s_bs + (uint32_t)(st*BST + n*36 + q*4)*4,
                     Bp + (long)(col0+n)*ldb + k0 + q*4, true);
            }
        } else {
#pragma unroll
            for (int it = 0; it < (32*(BN/4))/NTH; it++) {
                int i = tid + it*NTH;
                int k = i / (BN/4), nq = i % (BN/4);
                cp16(s_bs + (uint32_t)(st*BST + k*(BN+8) + nq*4)*4,
                     Bp + (long)(k0+k)*ldb + col0 + nq*4, true);
            }
        }
    };

    float acc[MC][4][4];
#pragma unroll
    for (int i = 0; i < MC; i++)
#pragma unroll
        for (int j = 0; j < 4; j++)
#pragma unroll
            for (int r = 0; r < 4; r++) acc[i][j][r] = 0.f;

    const int nk = K/32;
    stage_load(0, 0);
    cp_commit();
    if (nk > 1) stage_load(1, 32);
    cp_commit();

    for (int t = 0; t < nk; t++) {
        cp_wait1();
        __syncthreads();
        if (t + 2 < nk) stage_load((t+2)%3, (t+2)*32);
        cp_commit();

        const float* As_s = As + (t%3)*AST;
        const float* Bs_s = Bs + (t%3)*BST;

#pragma unroll
        for (int kk = 0; kk < 4; kk++) {
            uint32_t a[MC][4];
#pragma unroll
            for (int i = 0; i < MC; i++) {
                int r = wm*WM + i*16;
                a[i][0] = __float_as_uint(As_s[(r+g  )*36 + kk*8 + tg  ]);
                a[i][1] = __float_as_uint(As_s[(r+g+8)*36 + kk*8 + tg  ]);
                a[i][2] = __float_as_uint(As_s[(r+g  )*36 + kk*8 + tg+4]);
                a[i][3] = __float_as_uint(As_s[(r+g+8)*36 + kk*8 + tg+4]);
            }
            uint32_t b[4][2];
#pragma unroll
            for (int j = 0; j < 4; j++) {
                int n = wn*32 + j*8 + g;
                if (TRB) {
                    b[j][0] = __float_as_uint(Bs_s[n*36 + kk*8 + tg  ]);
                    b[j][1] = __float_as_uint(Bs_s[n*36 + kk*8 + tg+4]);
                } else {
                    b[j][0] = __float_as_uint(Bs_s[(kk*8 + tg  )*(BN+8) + n]);
                    b[j][1] = __float_as_uint(Bs_s[(kk*8 + tg+4)*(BN+8) + n]);
                }
            }
#pragma unroll
            for (int i = 0; i < MC; i++)
#pragma unroll
                for (int j = 0; j < 4; j++) {
                    asm volatile(
                        "mma.sync.aligned.m16n8k8.row.col.f32.tf32.tf32.f32 "
                        "{%0,%1,%2,%3}, {%4,%5,%6,%7}, {%8,%9}, {%0,%1,%2,%3};"
                        : "+f"(acc[i][j][0]), "+f"(acc[i][j][1]),
                          "+f"(acc[i][j][2]), "+f"(acc[i][j][3])
                        : "r"(a[i][0]), "r"(a[i][1]), "r"(a[i][2]), "r"(a[i][3]),
                          "r"(b[j][0]), "r"(b[j][1]));
                }
        }
    }

    // ---- epilogue ----
#pragma unroll
    for (int i = 0; i < MC; i++) {
        int r0 = row0 + wm*WM + i*16 + g;
#pragma unroll
        for (int rr = 0; rr < 2; rr++) {
            int gm = r0 + rr*8;
            if (gm >= Mrows) continue;
            float rb = (EPI == 3) ? bias[gm] : 0.f;
#pragma unroll
            for (int j = 0; j < 4; j++) {
                int cn = col0 + wn*32 + j*8 + 2*tg;
                float v0 = acc[i][j][rr*2 + 0];
                float v1 = acc[i][j][rr*2 + 1];
                if (EPI == 1)      { v0 += bias[cn]; v1 += bias[cn+1]; }
                else if (EPI == 2) { v0 = fmaxf(v0 + bias[cn], 0.f);
                                     v1 = fmaxf(v1 + bias[cn+1], 0.f); }
                else if (EPI == 3) { v0 = (v0 + rb) * scale; v1 = (v1 + rb) * scale; }
                *(float2*)(C + (long)gm*ldc + cn) = make_float2(v0, v1);
            }
        }
    }
}

// qb[bt,h] = sum_d Q[bt, h*64+d] * bK[h*64+d]
__global__ void qb_k(const float* __restrict__ Q, const float* __restrict__ bK,
                     float* __restrict__ qb)
{
    int idx = blockIdx.x*blockDim.x + threadIdx.x;
    if (idx >= BT_ROWS*HH) return;
    int bt = idx / HH, h = idx % HH;
    const float* q  = Q  + (long)bt*QD + h*HD;
    const float* bk = bK + h*HD;
    float s = 0.f;
#pragma unroll 8
    for (int d = 0; d < HD; d++) s = fmaf(q[d], bk[d], s);
    qb[idx] = s;
}

// in-place softmax over rows of length 2048
__global__ void softmax_k(float* __restrict__ attn)
{
    float* p = attn + (long)blockIdx.x * MM;
    int tid = threadIdx.x;
    int lane = tid & 31, w = tid >> 5;
    __shared__ float red[8];

    float v[8];
    float mx = -1e30f;
#pragma unroll
    for (int i = 0; i < 8; i++) { v[i] = p[tid + 256*i]; mx = fmaxf(mx, v[i]); }
#pragma unroll
    for (int o = 16; o; o >>= 1) mx = fmaxf(mx, __shfl_xor_sync(0xffffffffu, mx, o));
    if (lane == 0) red[w] = mx;
    __syncthreads();
    mx = red[0];
#pragma unroll
    for (int i = 1; i < 8; i++) mx = fmaxf(mx, red[i]);
    __syncthreads();

    float s = 0.f;
#pragma unroll
    for (int i = 0; i < 8; i++) { v[i] = __expf(v[i] - mx); s += v[i]; }
#pragma unroll
    for (int o = 16; o; o >>= 1) s += __shfl_xor_sync(0xffffffffu, s, o);
    if (lane == 0) red[w] = s;
    __syncthreads();
    float tot = 0.f;
#pragma unroll
    for (int i = 0; i < 8; i++) tot += red[i];

    float inv = 1.f / tot;
#pragma unroll
    for (int i = 0; i < 8; i++) p[tid + 256*i] = v[i] * inv;
}

// out[row,:] = LN(a[row,:] + b[row,:]) * g + be   (row length 768)
__global__ void ln_k(const float* __restrict__ a, const float* __restrict__ b,
                     const float* __restrict__ g, const float* __restrict__ be,
                     float* __restrict__ out)
{
    long row = blockIdx.x;
    int tid = threadIdx.x;
    int lane = tid & 31, w = tid >> 5;
    const float* pa = a + row*QD;
    const float* pb = b + row*QD;
    __shared__ float red[8];

    float v[3];
    float s = 0.f;
#pragma unroll
    for (int i = 0; i < 3; i++) { v[i] = pa[tid + 256*i] + pb[tid + 256*i]; s += v[i]; }
#pragma unroll
    for (int o = 16; o; o >>= 1) s += __shfl_xor_sync(0xffffffffu, s, o);
    if (lane == 0) red[w] = s;
    __syncthreads();
    float tot = 0.f;
#pragma unroll
    for (int i = 0; i < 8; i++) tot += red[i];
    float mu = tot * (1.f/768.f);
    __syncthreads();

    float sq = 0.f;
#pragma unroll
    for (int i = 0; i < 3; i++) { float d = v[i] - mu; sq = fmaf(d, d, sq); }
#pragma unroll
    for (int o = 16; o; o >>= 1) sq += __shfl_xor_sync(0xffffffffu, sq, o);
    if (lane == 0) red[w] = sq;
    __syncthreads();
    float vtot = 0.f;
#pragma unroll
    for (int i = 0; i < 8; i++) vtot += red[i];
    float inv = rsqrtf(vtot * (1.f/768.f) + 1e-5f);

#pragma unroll
    for (int i = 0; i < 3; i++) {
        int c = tid + 256*i;
        out[row*QD + c] = (v[i] - mu) * inv * g[c] + be[c];
    }
}

// smem byte sizes per instantiation (3 stages)
template<int BM, int BN, bool TRB>
constexpr int smem_bytes() {
    return 3 * (BM*36 + (TRB ? BN*36 : 32*(BN+8))) * 4;
}

extern "C" void kernel_launch(void* const* d_in, const int* in_sizes, int n_in,
                              void* d_out_v, int out_size)
{
    const float* expert = (const float*)d_in[0];
    const float* kv     = (const float*)d_in[1];
    const float* WQ  = (const float*)d_in[2];
    const float* bQ  = (const float*)d_in[3];
    const float* WK  = (const float*)d_in[4];
    const float* bK  = (const float*)d_in[5];
    const float* WV  = (const float*)d_in[6];
    const float* bV  = (const float*)d_in[7];
    const float* W1  = (const float*)d_in[8];
    const float* b1  = (const float*)d_in[9];
    const float* W2  = (const float*)d_in[10];
    const float* b2  = (const float*)d_in[11];
    const float* g1  = (const float*)d_in[12];
    const float* be1 = (const float*)d_in[13];
    const float* g2  = (const float*)d_in[14];
    const float* be2 = (const float*)d_in[15];

    float* out   = (float*)d_out_v;
    float* attnw = out + ((long)out_size - (long)NATTN);

    float *Q, *qb, *Qt, *ctx, *ao, *x, *hid, *y;
    cudaGetSymbolAddress((void**)&Q,   g_Q);
    cudaGetSymbolAddress((void**)&qb,  g_qb);
    cudaGetSymbolAddress((void**)&Qt,  g_Qt);
    cudaGetSymbolAddress((void**)&ctx, g_ctx);
    cudaGetSymbolAddress((void**)&ao,  g_ao);
    cudaGetSymbolAddress((void**)&x,   g_x);
    cudaGetSymbolAddress((void**)&hid, g_hid);
    cudaGetSymbolAddress((void**)&y,   g_y);

    cudaFuncSetAttribute(mma_gemm<32,128,32,false,1>, cudaFuncAttributeMaxDynamicSharedMemorySize, smem_bytes<32,128,false>());
    cudaFuncSetAttribute(mma_gemm<64,128,64,true, 0>, cudaFuncAttributeMaxDynamicSharedMemorySize, smem_bytes<64,128,true>());
    cudaFuncSetAttribute(mma_gemm<64,128,64,true, 3>, cudaFuncAttributeMaxDynamicSharedMemorySize, smem_bytes<64,128,true>());
    cudaFuncSetAttribute(mma_gemm<64,128,64,false,0>, cudaFuncAttributeMaxDynamicSharedMemorySize, smem_bytes<64,128,false>());
    cudaFuncSetAttribute(mma_gemm<64, 64,64,false,1>, cudaFuncAttributeMaxDynamicSharedMemorySize, smem_bytes<64,64,false>());
    cudaFuncSetAttribute(mma_gemm<64,128,64,false,2>, cudaFuncAttributeMaxDynamicSharedMemorySize, smem_bytes<64,128,false>());
    cudaFuncSetAttribute(mma_gemm<64,128,64,false,1>, cudaFuncAttributeMaxDynamicSharedMemorySize, smem_bytes<64,128,false>());

    // 1) Q projection (batched over t): Q[bt,q] = expert[b,t,:]@WQ[t] + bQ[t]
    mma_gemm<32,128,32,false,1><<<dim3(QD/128, 1, TT), 128, smem_bytes<32,128,false>()>>>(
        expert, TT*QD, (long)QD,
        WQ, QD, (long)QD*QD,
        Q, TT*QD, (long)QD,
        bQ, QD, BB, 1.f, QD);

    // 2) qb = per-head Q . bK
    qb_k<<<(BT_ROWS*HH)/256, 256>>>(Q, bK, qb);

    // 3) Qt[bt,h,c] = sum_d Q[bt,h*64+d] * WK[c,h*64+d]   (batched over h, NT)
    mma_gemm<64,128,64,true,0><<<dim3(KVD/128, 7, HH), 128, smem_bytes<64,128,true>()>>>(
        Q, QD, (long)HD,
        WK, QD, (long)HD,
        Qt, HH*KVD, (long)KVD,
        nullptr, 0, BT_ROWS, 1.f, HD);

    // 4) scores[b,(t,h),m] = (Qt . kv + qb) / 8   (batched over b, NT)
    mma_gemm<64,128,64,true,3><<<dim3(MM/128, 3, BB), 128, smem_bytes<64,128,true>()>>>(
        Qt, KVD, (long)RH*KVD,
        kv, KVD, (long)MM*KVD,
        attnw, MM, (long)RH*MM,
        qb, RH, RH, 0.125f, KVD);

    // 5) softmax over m (in place)
    softmax_k<<<BB*TT*HH, 256>>>(attnw);

    // 6) ctx[b,(t,h),c] = attn_w . kv   (batched over b, NN)
    mma_gemm<64,128,64,false,0><<<dim3(KVD/128, 3, BB), 128, smem_bytes<64,128,false>()>>>(
        attnw, MM, (long)RH*MM,
        kv, KVD, (long)MM*KVD,
        ctx, KVD, (long)RH*KVD,
        nullptr, 0, RH, 1.f, MM);

    // 7) attn_out[bt, h*64+n] = ctx[bt,h,:] @ WV[:, h*64+n] + bV  (batched over h)
    mma_gemm<64,64,64,false,1><<<dim3(1, 7, HH), 64, smem_bytes<64,64,false>()>>>(
        ctx, HH*KVD, (long)KVD,
        WV, QD, (long)HD,
        ao, QD, (long)HD,
        bV, HD, BT_ROWS, 1.f, KVD);

    // 8) x = LN1(expert + attn_out)
    ln_k<<<BT_ROWS, 256>>>(expert, ao, g1, be1, x);

    // 9) hidden = relu(x @ W1 + b1)
    mma_gemm<64,128,64,false,2><<<dim3(FFD/128, 7, 1), 128, smem_bytes<64,128,false>()>>>(
        x, QD, 0,
        W1, FFD, 0,
        hid, FFD, 0,
        b1, 0, BT_ROWS, 1.f, QD);

    // 10) y = hidden @ W2 + b2
    mma_gemm<64,128,64,false,1><<<dim3(QD/128, 7, 1), 128, smem_bytes<64,128,false>()>>>(
        hid, FFD, 0,
        W2, QD, 0,
        y, QD, 0,
        b2, 0, BT_ROWS, 1.f, FFD);

    // 11) out = LN2(x + y)
    ln_k<<<BT_ROWS, 256>>>(x, y, g2, be2, out);
}